// round 12
// baseline (speedup 1.0000x reference)
#include <cuda_runtime.h>
#include <cuda_fp16.h>
#include <mma.h>
#include <math.h>

using namespace nvcuda;

#define NN 100000
#define EE 1000000
#define BGRID 592   // 4 blocks/SM x 148 SMs -- co-resident (256 thr, low regs)

// Scratch (device globals — no allocation allowed)
__device__ int   g_is32;
__device__ int   g_ctr;
__device__ int   g_gen;     // barrier generation (monotonic across replays)
__device__ int   g_cnt;     // barrier arrival counter (self-resetting)
__device__ int   g_csr[EE];
__device__ int   g_degi[NN];
__device__ int   g_off[NN];
__device__ int   g_cur[NN];
__device__ float g_dinv[NN];
__device__ __align__(16) float  g_b1p[112];
__device__ __align__(16) float  g_b2p[64];
__device__ __align__(16) __half g_w1h[64 * 112];
__device__ __align__(16) __half g_w2h[112 * 64];
__device__ __align__(16) __half g_w3h[64 * 32];
__device__ __align__(16) __half g_hx[(size_t)NN * 64];
__device__ __align__(16) __half g_h1[(size_t)NN * 64];
__device__ __align__(16) __half g_h2[(size_t)NN * 112];

// ---------------- grid barrier (all BGRID blocks co-resident) ----------------
__device__ __forceinline__ void gsync() {
    __threadfence();
    __syncthreads();
    if (threadIdx.x == 0) {
        int g = atomicAdd(&g_gen, 0);
        if (atomicAdd(&g_cnt, 1) == BGRID - 1) {
            atomicExch(&g_cnt, 0);
            __threadfence();
            atomicAdd(&g_gen, 1);
        } else {
            while (atomicAdd(&g_gen, 0) == g) __nanosleep(64);
        }
    }
    __syncthreads();
}

// ---------------- fused build: setup + count + alloc + fill + padw ----------------
__global__ void __launch_bounds__(256, 4) k_build(
    const float* __restrict__ x, __half* __restrict__ xh,
    const void* __restrict__ edge, int E,
    const float* __restrict__ W1, const float* __restrict__ W2,
    const float* __restrict__ W3, const float* __restrict__ b1,
    const float* __restrict__ b2) {
    int tid = blockIdx.x * blockDim.x + threadIdx.x;
    int NT = gridDim.x * blockDim.x;

    // ---- phase 0: zero + detect + x->half + weight pad ----
    if (blockIdx.x == 0) {
        if (threadIdx.x == 0) { g_is32 = 0; g_ctr = 0; }
        __syncthreads();
        const long long* e64 = (const long long*)edge;
        int nscan = E < 4096 ? E : 4096;
        for (int j = threadIdx.x; j < nscan; j += blockDim.x) {
            long long v = e64[j];
            if (v < 0 || v >= NN) g_is32 = 1;  // benign race
        }
    }
    for (int i = tid; i < NN; i += NT) g_degi[i] = 0;
    for (int i = tid; i < NN * 8; i += NT) {
        float4 a = *(const float4*)(x + (size_t)i * 8);
        float4 b = *(const float4*)(x + (size_t)i * 8 + 4);
        __half2 h[4];
        h[0] = __float22half2_rn(make_float2(a.x, a.y));
        h[1] = __float22half2_rn(make_float2(a.z, a.w));
        h[2] = __float22half2_rn(make_float2(b.x, b.y));
        h[3] = __float22half2_rn(make_float2(b.z, b.w));
        *(uint4*)(xh + (size_t)i * 8) = *(uint4*)h;
    }
    for (int i = tid; i < 64 * 112; i += NT) {
        int r = i / 112, c = i - r * 112;
        g_w1h[i] = __float2half(c < 100 ? W1[r * 100 + c] : 0.0f);
    }
    for (int i = tid; i < 112 * 64; i += NT) {
        int r = i / 64, c = i - r * 64;
        g_w2h[i] = __float2half((r < 100 && c < 50) ? W2[r * 50 + c] : 0.0f);
    }
    for (int i = tid; i < 64 * 32; i += NT) {
        int r = i / 32, c = i - r * 32;
        g_w3h[i] = __float2half((r < 50 && c < 25) ? W3[r * 25 + c] : 0.0f);
    }
    if (tid < 112) g_b1p[tid] = (tid < 100) ? b1[tid] : 0.0f;
    if (tid < 64)  g_b2p[tid] = (tid < 50)  ? b2[tid] : 0.0f;

    gsync();

    // ---- phase 1: degree count ----
    bool is32 = g_is32;
    const int* p32 = (const int*)edge;
    const long long* p64 = (const long long*)edge;
    for (int e = tid; e < E; e += NT) {
        int d = is32 ? p32[E + e] : (int)p64[E + e];
        atomicAdd(&g_degi[d], 1);
    }

    gsync();

    // ---- phase 2: dinv + unordered segment alloc ----
    for (int i = tid; i < NN; i += NT) {
        int d = g_degi[i];
        g_dinv[i] = rsqrtf((float)d + 1.0f);  // +1 self loop
        int off = atomicAdd(&g_ctr, d);
        g_off[i] = off;
        g_cur[i] = off;
    }

    gsync();

    // ---- phase 3: CSR fill (unroll x2 for atomic-latency overlap) ----
    int e = tid;
    for (; e + NT < E; e += 2 * NT) {
        int e2 = e + NT;
        int s0, d0, s1, d1;
        if (is32) {
            s0 = p32[e];  d0 = p32[E + e];
            s1 = p32[e2]; d1 = p32[E + e2];
        } else {
            s0 = (int)p64[e];  d0 = (int)p64[E + e];
            s1 = (int)p64[e2]; d1 = (int)p64[E + e2];
        }
        int q0 = atomicAdd(&g_cur[d0], 1);
        int q1 = atomicAdd(&g_cur[d1], 1);
        g_csr[q0] = s0;
        g_csr[q1] = s1;
    }
    if (e < E) {
        int s0, d0;
        if (is32) { s0 = p32[e]; d0 = p32[E + e]; }
        else      { s0 = (int)p64[e]; d0 = (int)p64[E + e]; }
        int q0 = atomicAdd(&g_cur[d0], 1);
        g_csr[q0] = s0;
    }
}

__device__ __forceinline__ void fma_half8(float* acc, uint4 raw, float w) {
    const __half2* hp = (const __half2*)&raw;
#pragma unroll
    for (int j = 0; j < 4; j++) {
        float2 f = __half22float2(hp[j]);
        acc[2 * j]     = fmaf(f.x, w, acc[2 * j]);
        acc[2 * j + 1] = fmaf(f.y, w, acc[2 * j + 1]);
    }
}

// ---------------- gather aggregation (half payload, fp32 accum, half out) ----------------
template <int C, int LD, bool BR>
__global__ void k_aggh(const __half* __restrict__ xh, __half* __restrict__ outh,
                       const float* __restrict__ bias) {
    int idx = blockIdx.x * blockDim.x + threadIdx.x;
    if (idx >= NN * C) return;
    int i = idx / C;
    int c = idx - i * C;
    float di = g_dinv[i];
    float s2 = di * di;
    float acc[8];
    {
        uint4 raw = *(const uint4*)(xh + (size_t)i * LD + c * 8);
        const __half2* hp = (const __half2*)&raw;
#pragma unroll
        for (int j = 0; j < 4; j++) {
            float2 f = __half22float2(hp[j]);
            acc[2 * j]     = f.x * s2;
            acc[2 * j + 1] = f.y * s2;
        }
    }
    int b = g_off[i];
    int e = b + g_degi[i];
    int t = b;
    for (; t + 2 <= e; t += 2) {
        int s0 = g_csr[t];
        int s1 = g_csr[t + 1];
        float w0 = g_dinv[s0] * di;
        float w1 = g_dinv[s1] * di;
        uint4 r0 = *(const uint4*)(xh + (size_t)s0 * LD + c * 8);
        uint4 r1 = *(const uint4*)(xh + (size_t)s1 * LD + c * 8);
        fma_half8(acc, r0, w0);
        fma_half8(acc, r1, w1);
    }
    if (t < e) {
        int s0 = g_csr[t];
        float w0 = g_dinv[s0] * di;
        uint4 r0 = *(const uint4*)(xh + (size_t)s0 * LD + c * 8);
        fma_half8(acc, r0, w0);
    }
    if (BR) {
#pragma unroll
        for (int j = 0; j < 8; j++)
            acc[j] = fmaxf(acc[j] + bias[c * 8 + j], 0.0f);
    }
    __half2 h[4];
#pragma unroll
    for (int j = 0; j < 4; j++)
        h[j] = __float22half2_rn(make_float2(acc[2 * j], acc[2 * j + 1]));
    *(uint4*)(outh + (size_t)i * LD + c * 8) = *(uint4*)h;
}

// ---------------- wmma GEMM: Yh = [relu](Xh @ Wh [+ b]) ----------------
template <int KP, int NP, bool BR>
__global__ void k_gemm_wmma(const __half* __restrict__ X, const __half* __restrict__ W,
                            const float* __restrict__ bias, __half* __restrict__ Yh, int n) {
    constexpr int NT = NP / 16, KT = KP / 16;
    constexpr int SM_AB = 64 * KP * 2 + KP * NP * 2;
    constexpr int SM_O  = 64 * NP * 4;
    constexpr int SM = SM_AB > SM_O ? SM_AB : SM_O;
    __shared__ __align__(32) char sm[SM];
    __half* Xs = (__half*)sm;                       // [64, KP]
    __half* Ws = (__half*)(sm + 64 * KP * 2);       // [KP, NP]
    float*  Os = (float*)sm;                        // reused after K loop: [64, NP]

    int tid = threadIdx.x;
    int wid = tid >> 5;
    int base = blockIdx.x * 64;

    for (int i = tid; i < KP * NP / 8; i += blockDim.x)
        ((uint4*)Ws)[i] = ((const uint4*)W)[i];
    constexpr int RW = KP / 8;  // uint4 per row
    for (int i = tid; i < 64 * RW; i += blockDim.x) {
        int r = i / RW, c = i - r * RW;
        uint4 v = {0, 0, 0, 0};
        if (base + r < n) v = ((const uint4*)(X + (size_t)(base + r) * KP))[c];
        ((uint4*)Xs)[i] = v;
    }
    __syncthreads();

    wmma::fragment<wmma::accumulator, 16, 16, 16, float> cf[NT];
#pragma unroll
    for (int nt = 0; nt < NT; nt++) wmma::fill_fragment(cf[nt], 0.0f);

#pragma unroll
    for (int kt = 0; kt < KT; kt++) {
        wmma::fragment<wmma::matrix_a, 16, 16, 16, __half, wmma::row_major> af;
        wmma::load_matrix_sync(af, Xs + wid * 16 * KP + kt * 16, KP);
#pragma unroll
        for (int nt = 0; nt < NT; nt++) {
            wmma::fragment<wmma::matrix_b, 16, 16, 16, __half, wmma::row_major> bf;
            wmma::load_matrix_sync(bf, Ws + kt * 16 * NP + nt * 16, NP);
            wmma::mma_sync(cf[nt], af, bf, cf[nt]);
        }
    }
    __syncthreads();  // done with Xs/Ws; alias as Os
#pragma unroll
    for (int nt = 0; nt < NT; nt++)
        wmma::store_matrix_sync(Os + wid * 16 * NP + nt * 16, cf[nt], NP, wmma::mem_row_major);
    __syncthreads();

    constexpr int CW = NP / 4;  // float4 groups per row
    for (int i = tid; i < 64 * CW; i += blockDim.x) {
        int r = i / CW, c = i - r * CW;
        if (base + r >= n) continue;
        float4 v = ((const float4*)(Os + r * NP))[c];
        if (BR) {
            float4 bb = *(const float4*)(bias + c * 4);
            v.x = fmaxf(v.x + bb.x, 0.0f); v.y = fmaxf(v.y + bb.y, 0.0f);
            v.z = fmaxf(v.z + bb.z, 0.0f); v.w = fmaxf(v.w + bb.w, 0.0f);
        }
        __half2 h01 = __float22half2_rn(make_float2(v.x, v.y));
        __half2 h23 = __float22half2_rn(make_float2(v.z, v.w));
        uint2 pk = {*(unsigned*)&h01, *(unsigned*)&h23};
        *(uint2*)(Yh + (size_t)(base + r) * NP + c * 4) = pk;
    }
}

// ---------------- fused agg3 + epilogue MLP: one thread per node ----------------
__global__ void k_agg3_final(const __half* __restrict__ xh, const float* __restrict__ b3,
                             const float* __restrict__ Wl1, const float* __restrict__ bl1,
                             const float* __restrict__ Wl2, const float* __restrict__ bl2,
                             const float* __restrict__ Wl3, const float* __restrict__ bl3,
                             float* __restrict__ out, int n) {
    __shared__ float sW1[25 * 25], sW2[25 * 10], sW3[10];
    __shared__ float sb3[25], sb1[25], sb2[10], sb3l;
    for (int i = threadIdx.x; i < 25 * 25; i += blockDim.x) sW1[i] = Wl1[i];
    for (int i = threadIdx.x; i < 25 * 10; i += blockDim.x) sW2[i] = Wl2[i];
    if (threadIdx.x < 10) sW3[threadIdx.x] = Wl3[threadIdx.x];
    if (threadIdx.x < 25) { sb3[threadIdx.x] = b3[threadIdx.x]; sb1[threadIdx.x] = bl1[threadIdx.x]; }
    if (threadIdx.x < 10) sb2[threadIdx.x] = bl2[threadIdx.x];
    if (threadIdx.x == 0) sb3l = bl3[0];
    __syncthreads();

    int i = blockIdx.x * blockDim.x + threadIdx.x;
    if (i >= n) return;

    float di = g_dinv[i];
    float s2 = di * di;
    float acc[32];
    {
        const uint4* p = (const uint4*)(xh + (size_t)i * 32);
#pragma unroll
        for (int q = 0; q < 4; q++) {
            uint4 raw = p[q];
            const __half2* hp = (const __half2*)&raw;
#pragma unroll
            for (int j = 0; j < 4; j++) {
                float2 f = __half22float2(hp[j]);
                acc[q * 8 + 2 * j]     = f.x * s2;
                acc[q * 8 + 2 * j + 1] = f.y * s2;
            }
        }
    }
    int b = g_off[i];
    int e = b + g_degi[i];
    for (int t = b; t < e; t++) {
        int s = g_csr[t];
        float w = g_dinv[s] * di;
        const uint4* p = (const uint4*)(xh + (size_t)s * 32);
        uint4 r0 = p[0], r1 = p[1], r2 = p[2], r3 = p[3];
        fma_half8(acc,      r0, w);
        fma_half8(acc + 8,  r1, w);
        fma_half8(acc + 16, r2, w);
        fma_half8(acc + 24, r3, w);
    }

    float v[25];
#pragma unroll
    for (int f = 0; f < 25; f++)
        v[f] = fmaxf(acc[f] + sb3[f], 0.0f);

    float h1[25];
#pragma unroll
    for (int c = 0; c < 25; c++) {
        float a = sb1[c];
#pragma unroll
        for (int k = 0; k < 25; k++) a = fmaf(v[k], sW1[k * 25 + c], a);
        h1[c] = fmaxf(a, 0.0f);
    }
    float h2[10];
#pragma unroll
    for (int c = 0; c < 10; c++) {
        float a = sb2[c];
#pragma unroll
        for (int k = 0; k < 25; k++) a = fmaf(h1[k], sW2[k * 10 + c], a);
        h2[c] = fmaxf(a, 0.0f);
    }
    float o = sb3l;
#pragma unroll
    for (int k = 0; k < 10; k++) o = fmaf(h2[k], sW3[k], o);
    out[i] = fmaxf(o, 0.0f);
}

// ---------------- launch ----------------
extern "C" void kernel_launch(void* const* d_in, const int* in_sizes, int n_in,
                              void* d_out, int out_size) {
    const float* x   = (const float*)d_in[0];
    const float* W1  = (const float*)d_in[1];
    const float* b1  = (const float*)d_in[2];
    const float* W2  = (const float*)d_in[3];
    const float* b2  = (const float*)d_in[4];
    const float* W3  = (const float*)d_in[5];
    const float* b3  = (const float*)d_in[6];
    const float* Wl1 = (const float*)d_in[7];
    const float* bl1 = (const float*)d_in[8];
    const float* Wl2 = (const float*)d_in[9];
    const float* bl2 = (const float*)d_in[10];
    const float* Wl3 = (const float*)d_in[11];
    const float* bl3 = (const float*)d_in[12];
    const void* edge = d_in[13];
    int E = in_sizes[13] / 2;

    float *b1p, *b2p;
    __half *HX, *H1, *H2, *W1H, *W2H, *W3H;
    cudaGetSymbolAddress((void**)&b1p, g_b1p);
    cudaGetSymbolAddress((void**)&b2p, g_b2p);
    cudaGetSymbolAddress((void**)&HX,  g_hx);
    cudaGetSymbolAddress((void**)&H1,  g_h1);
    cudaGetSymbolAddress((void**)&H2,  g_h2);
    cudaGetSymbolAddress((void**)&W1H, g_w1h);
    cudaGetSymbolAddress((void**)&W2H, g_w2h);
    cudaGetSymbolAddress((void**)&W3H, g_w3h);

    const int T = 256;
    int gN = (NN + T - 1) / T;

    // fused preprocessing: setup + count + alloc + fill + weight prep (1 launch)
    k_build<<<BGRID, T>>>(x, HX, edge, E, W1, W2, W3, b1, b2);

    int gemmG = (NN + 63) / 64;

    // ----- Layer 1: agg (64) -> half; wmma 64->112 (+b1,relu) -----
    k_aggh<8, 64, false><<<NN * 8 / T, T>>>(HX, H1, nullptr);
    k_gemm_wmma<64, 112, true><<<gemmG, 128>>>(H1, W1H, b1p, H2, NN);

    // ----- Layer 2: wmma 112->64 raw; agg (64) +b2,relu -----
    k_gemm_wmma<112, 64, false><<<gemmG, 128>>>(H2, W2H, nullptr, HX, NN);
    k_aggh<8, 64, true><<<NN * 8 / T, T>>>(HX, H1, b2p);

    // ----- Layer 3: wmma 64->32 raw; fused agg (32) + MLP epilogue -----
    k_gemm_wmma<64, 32, false><<<gemmG, 128>>>(H1, W3H, nullptr, H2, NN);
    k_agg3_final<<<gN, T>>>(H2, b3, Wl1, bl1, Wl2, bl2, Wl3, bl3, (float*)d_out, NN);
}

// round 13
// speedup vs baseline: 1.2562x; 1.2562x over previous
#include <cuda_runtime.h>
#include <cuda_fp16.h>
#include <mma.h>
#include <math.h>

using namespace nvcuda;

#define NN 100000
#define EE 1000000

// Scratch (device globals — no allocation allowed)
__device__ int   g_is32;
__device__ int   g_ctr;
__device__ int   g_csr[EE];
__device__ int   g_degi[NN];
__device__ int   g_off[NN];
__device__ int   g_cur[NN];
__device__ float g_dinv[NN];
__device__ __align__(16) float  g_b1p[112];
__device__ __align__(16) float  g_b2p[64];
__device__ __align__(16) __half g_w1h[64 * 112];
__device__ __align__(16) __half g_w2h[112 * 64];
__device__ __align__(16) __half g_w3h[64 * 32];
__device__ __align__(16) __half g_hx[(size_t)NN * 64];
__device__ __align__(16) __half g_h1[(size_t)NN * 64];
__device__ __align__(16) __half g_h2[(size_t)NN * 112];

// ---------------- setup: zero deg/ctr + dtype detect + x->half ----------------
__global__ void k_setup(const float* __restrict__ x, __half* __restrict__ xh,
                        const long long* __restrict__ edge64, int E) {
    int idx = blockIdx.x * blockDim.x + threadIdx.x;
    if (idx < NN) g_degi[idx] = 0;
    if (idx < NN * 8) {
        float4 a = *(const float4*)(x + (size_t)idx * 8);
        float4 b = *(const float4*)(x + (size_t)idx * 8 + 4);
        __half2 h[4];
        h[0] = __float22half2_rn(make_float2(a.x, a.y));
        h[1] = __float22half2_rn(make_float2(a.z, a.w));
        h[2] = __float22half2_rn(make_float2(b.x, b.y));
        h[3] = __float22half2_rn(make_float2(b.z, b.w));
        *(uint4*)(xh + (size_t)idx * 8) = *(uint4*)h;
    }
    if (blockIdx.x == 0) {
        if (threadIdx.x == 0) { g_is32 = 0; g_ctr = 0; }
        __syncthreads();
        int nscan = E < 4096 ? E : 4096;
        for (int j = threadIdx.x; j < nscan; j += blockDim.x) {
            long long v = edge64[j];
            if (v < 0 || v >= NN) g_is32 = 1;  // benign race
        }
    }
}

// ---------------- degree count ----------------
__global__ void k_count(const void* __restrict__ edge, int E) {
    int e = blockIdx.x * blockDim.x + threadIdx.x;
    if (e >= E) return;
    int d = g_is32 ? ((const int*)edge)[E + e]
                   : (int)((const long long*)edge)[E + e];
    atomicAdd(&g_degi[d], 1);
}

// ---------------- segment allocation (unordered CSR) + dinv ----------------
__global__ void k_alloc() {
    int i = blockIdx.x * blockDim.x + threadIdx.x;
    if (i >= NN) return;
    int d = g_degi[i];
    g_dinv[i] = rsqrtf((float)d + 1.0f);  // +1 self loop
    int off = atomicAdd(&g_ctr, d);
    g_off[i] = off;
    g_cur[i] = off;
}

// ---------------- CSR fill ----------------
__global__ void k_fill(const void* __restrict__ edge, int E) {
    int e = blockIdx.x * blockDim.x + threadIdx.x;
    if (e >= E) return;
    int s, d;
    if (g_is32) {
        const int* p = (const int*)edge;
        s = p[e]; d = p[E + e];
    } else {
        const long long* p = (const long long*)edge;
        s = (int)p[e]; d = (int)p[E + e];
    }
    int pos = atomicAdd(&g_cur[d], 1);
    g_csr[pos] = s;
}

// ---------------- weight/bias pad+convert (once per launch) ----------------
__global__ void k_padw(const float* __restrict__ W1, const float* __restrict__ W2,
                       const float* __restrict__ W3, const float* __restrict__ b1,
                       const float* __restrict__ b2) {
    int i = blockIdx.x * blockDim.x + threadIdx.x;
    if (i < 64 * 112) {
        int r = i / 112, c = i - r * 112;
        g_w1h[i] = __float2half(c < 100 ? W1[r * 100 + c] : 0.0f);
    } else if (i < 64 * 112 + 112 * 64) {
        int j = i - 64 * 112;
        int r = j / 64, c = j - r * 64;
        g_w2h[j] = __float2half((r < 100 && c < 50) ? W2[r * 50 + c] : 0.0f);
    } else if (i < 64 * 112 + 112 * 64 + 64 * 32) {
        int j = i - 64 * 112 - 112 * 64;
        int r = j / 32, c = j - r * 32;
        g_w3h[j] = __float2half((r < 50 && c < 25) ? W3[r * 25 + c] : 0.0f);
    }
    if (i < 112) g_b1p[i] = (i < 100) ? b1[i] : 0.0f;
    if (i < 64)  g_b2p[i] = (i < 50)  ? b2[i] : 0.0f;
}

__device__ __forceinline__ void fma_half8(float* acc, uint4 raw, float w) {
    const __half2* hp = (const __half2*)&raw;
#pragma unroll
    for (int j = 0; j < 4; j++) {
        float2 f = __half22float2(hp[j]);
        acc[2 * j]     = fmaf(f.x, w, acc[2 * j]);
        acc[2 * j + 1] = fmaf(f.y, w, acc[2 * j + 1]);
    }
}

// ---------------- gather aggregation (half payload, fp32 accum, half out) ----------------
template <int C, int LD, bool BR>
__global__ void k_aggh(const __half* __restrict__ xh, __half* __restrict__ outh,
                       const float* __restrict__ bias) {
    int idx = blockIdx.x * blockDim.x + threadIdx.x;
    if (idx >= NN * C) return;
    int i = idx / C;
    int c = idx - i * C;
    float di = g_dinv[i];
    float s2 = di * di;
    float acc[8];
    {
        uint4 raw = *(const uint4*)(xh + (size_t)i * LD + c * 8);
        const __half2* hp = (const __half2*)&raw;
#pragma unroll
        for (int j = 0; j < 4; j++) {
            float2 f = __half22float2(hp[j]);
            acc[2 * j]     = f.x * s2;
            acc[2 * j + 1] = f.y * s2;
        }
    }
    int b = g_off[i];
    int e = b + g_degi[i];
    int t = b;
    for (; t + 2 <= e; t += 2) {
        int s0 = g_csr[t];
        int s1 = g_csr[t + 1];
        float w0 = g_dinv[s0] * di;
        float w1 = g_dinv[s1] * di;
        uint4 r0 = *(const uint4*)(xh + (size_t)s0 * LD + c * 8);
        uint4 r1 = *(const uint4*)(xh + (size_t)s1 * LD + c * 8);
        fma_half8(acc, r0, w0);
        fma_half8(acc, r1, w1);
    }
    if (t < e) {
        int s0 = g_csr[t];
        float w0 = g_dinv[s0] * di;
        uint4 r0 = *(const uint4*)(xh + (size_t)s0 * LD + c * 8);
        fma_half8(acc, r0, w0);
    }
    if (BR) {
#pragma unroll
        for (int j = 0; j < 8; j++)
            acc[j] = fmaxf(acc[j] + bias[c * 8 + j], 0.0f);
    }
    __half2 h[4];
#pragma unroll
    for (int j = 0; j < 4; j++)
        h[j] = __float22half2_rn(make_float2(acc[2 * j], acc[2 * j + 1]));
    *(uint4*)(outh + (size_t)i * LD + c * 8) = *(uint4*)h;
}

// ---------------- wmma GEMM v2: padded smem (conflict-free) + RT row tiles ----------------
// Yh = [relu](Xh @ Wh [+ b]). X: [n, KP] half. W: [KP, NP] half (dense).
// 4 warps/block, each warp owns RT row-tiles of 16 rows. Strides padded +8 halves.
template <int KP, int NP, int RT, bool BR>
__global__ void k_gemm_wmma(const __half* __restrict__ X, const __half* __restrict__ W,
                            const float* __restrict__ bias, __half* __restrict__ Yh, int n) {
    constexpr int WARPS = 4;
    constexpr int ROWS = WARPS * RT * 16;
    constexpr int NT = NP / 16, KT = KP / 16;
    constexpr int XSP = KP + 8;     // padded X stride (halves)
    constexpr int NPP = NP + 8;     // padded W stride (halves)
    constexpr int SM_AB = ROWS * XSP * 2 + KP * NPP * 2;
    constexpr int SM_ST = WARPS * 16 * NP * 4;
    constexpr int SM = SM_AB > SM_ST ? SM_AB : SM_ST;
    __shared__ __align__(16) char sm[SM];
    __half* Xs = (__half*)sm;
    __half* Ws = (__half*)(sm + ROWS * XSP * 2);

    int tid = threadIdx.x;
    int wid = tid >> 5;
    int lane = tid & 31;
    int base = blockIdx.x * ROWS;

    // load W [KP x NP] -> Ws (stride NPP)
    for (int i = tid; i < KP * (NP / 8); i += blockDim.x) {
        int r = i / (NP / 8), g = i - r * (NP / 8);
        *(uint4*)(Ws + r * NPP + g * 8) = ((const uint4*)(W + r * NP))[g];
    }
    // load X rows -> Xs (stride XSP), zero-pad tail rows
    for (int i = tid; i < ROWS * (KP / 8); i += blockDim.x) {
        int r = i / (KP / 8), g = i - r * (KP / 8);
        uint4 v = {0, 0, 0, 0};
        if (base + r < n) v = ((const uint4*)(X + (size_t)(base + r) * KP))[g];
        *(uint4*)(Xs + r * XSP + g * 8) = v;
    }
    __syncthreads();

    wmma::fragment<wmma::accumulator, 16, 16, 16, float> cf[RT][NT];
#pragma unroll
    for (int rt = 0; rt < RT; rt++)
#pragma unroll
        for (int nt = 0; nt < NT; nt++) wmma::fill_fragment(cf[rt][nt], 0.0f);

    int wr = wid * RT * 16;
#pragma unroll
    for (int kt = 0; kt < KT; kt++) {
        wmma::fragment<wmma::matrix_a, 16, 16, 16, __half, wmma::row_major> af[RT];
#pragma unroll
        for (int rt = 0; rt < RT; rt++)
            wmma::load_matrix_sync(af[rt], Xs + (wr + rt * 16) * XSP + kt * 16, XSP);
#pragma unroll
        for (int nt = 0; nt < NT; nt++) {
            wmma::fragment<wmma::matrix_b, 16, 16, 16, __half, wmma::row_major> bf;
            wmma::load_matrix_sync(bf, Ws + kt * 16 * NPP + nt * 16, NPP);
#pragma unroll
            for (int rt = 0; rt < RT; rt++)
                wmma::mma_sync(cf[rt][nt], af[rt], bf, cf[rt][nt]);
        }
    }
    __syncthreads();  // done with Xs/Ws; alias per-warp staging over sm

    float* stg = (float*)sm + wid * 16 * NP;
#pragma unroll
    for (int rt = 0; rt < RT; rt++) {
#pragma unroll
        for (int nt = 0; nt < NT; nt++)
            wmma::store_matrix_sync(stg + nt * 16, cf[rt][nt], NP, wmma::mem_row_major);
        __syncwarp();
        int rbase = base + wr + rt * 16;
        for (int i = lane; i < 16 * (NP / 4); i += 32) {
            int r = i / (NP / 4), c = i - r * (NP / 4);
            if (rbase + r < n) {
                float4 v = *(const float4*)(stg + r * NP + c * 4);
                if (BR) {
                    float4 bb = *(const float4*)(bias + c * 4);
                    v.x = fmaxf(v.x + bb.x, 0.0f); v.y = fmaxf(v.y + bb.y, 0.0f);
                    v.z = fmaxf(v.z + bb.z, 0.0f); v.w = fmaxf(v.w + bb.w, 0.0f);
                }
                __half2 h01 = __float22half2_rn(make_float2(v.x, v.y));
                __half2 h23 = __float22half2_rn(make_float2(v.z, v.w));
                uint2 pk = {*(unsigned*)&h01, *(unsigned*)&h23};
                *(uint2*)(Yh + (size_t)(rbase + r) * NP + c * 4) = pk;
            }
        }
        __syncwarp();
    }
}

// ---------------- fused agg3 + epilogue MLP: one thread per node ----------------
__global__ void k_agg3_final(const __half* __restrict__ xh, const float* __restrict__ b3,
                             const float* __restrict__ Wl1, const float* __restrict__ bl1,
                             const float* __restrict__ Wl2, const float* __restrict__ bl2,
                             const float* __restrict__ Wl3, const float* __restrict__ bl3,
                             float* __restrict__ out, int n) {
    __shared__ float sW1[25 * 25], sW2[25 * 10], sW3[10];
    __shared__ float sb3[25], sb1[25], sb2[10], sb3l;
    for (int i = threadIdx.x; i < 25 * 25; i += blockDim.x) sW1[i] = Wl1[i];
    for (int i = threadIdx.x; i < 25 * 10; i += blockDim.x) sW2[i] = Wl2[i];
    if (threadIdx.x < 10) sW3[threadIdx.x] = Wl3[threadIdx.x];
    if (threadIdx.x < 25) { sb3[threadIdx.x] = b3[threadIdx.x]; sb1[threadIdx.x] = bl1[threadIdx.x]; }
    if (threadIdx.x < 10) sb2[threadIdx.x] = bl2[threadIdx.x];
    if (threadIdx.x == 0) sb3l = bl3[0];
    __syncthreads();

    int i = blockIdx.x * blockDim.x + threadIdx.x;
    if (i >= n) return;

    float di = g_dinv[i];
    float s2 = di * di;
    float acc[32];
    {
        const uint4* p = (const uint4*)(xh + (size_t)i * 32);
#pragma unroll
        for (int q = 0; q < 4; q++) {
            uint4 raw = p[q];
            const __half2* hp = (const __half2*)&raw;
#pragma unroll
            for (int j = 0; j < 4; j++) {
                float2 f = __half22float2(hp[j]);
                acc[q * 8 + 2 * j]     = f.x * s2;
                acc[q * 8 + 2 * j + 1] = f.y * s2;
            }
        }
    }
    int b = g_off[i];
    int e = b + g_degi[i];
    for (int t = b; t < e; t++) {
        int s = g_csr[t];
        float w = g_dinv[s] * di;
        const uint4* p = (const uint4*)(xh + (size_t)s * 32);
        uint4 r0 = p[0], r1 = p[1], r2 = p[2], r3 = p[3];
        fma_half8(acc,      r0, w);
        fma_half8(acc + 8,  r1, w);
        fma_half8(acc + 16, r2, w);
        fma_half8(acc + 24, r3, w);
    }

    float v[25];
#pragma unroll
    for (int f = 0; f < 25; f++)
        v[f] = fmaxf(acc[f] + sb3[f], 0.0f);

    float h1[25];
#pragma unroll
    for (int c = 0; c < 25; c++) {
        float a = sb1[c];
#pragma unroll
        for (int k = 0; k < 25; k++) a = fmaf(v[k], sW1[k * 25 + c], a);
        h1[c] = fmaxf(a, 0.0f);
    }
    float h2[10];
#pragma unroll
    for (int c = 0; c < 10; c++) {
        float a = sb2[c];
#pragma unroll
        for (int k = 0; k < 25; k++) a = fmaf(h1[k], sW2[k * 10 + c], a);
        h2[c] = fmaxf(a, 0.0f);
    }
    float o = sb3l;
#pragma unroll
    for (int k = 0; k < 10; k++) o = fmaf(h2[k], sW3[k], o);
    out[i] = fmaxf(o, 0.0f);
}

// ---------------- launch ----------------
extern "C" void kernel_launch(void* const* d_in, const int* in_sizes, int n_in,
                              void* d_out, int out_size) {
    const float* x   = (const float*)d_in[0];
    const float* W1  = (const float*)d_in[1];
    const float* b1  = (const float*)d_in[2];
    const float* W2  = (const float*)d_in[3];
    const float* b2  = (const float*)d_in[4];
    const float* W3  = (const float*)d_in[5];
    const float* b3  = (const float*)d_in[6];
    const float* Wl1 = (const float*)d_in[7];
    const float* bl1 = (const float*)d_in[8];
    const float* Wl2 = (const float*)d_in[9];
    const float* bl2 = (const float*)d_in[10];
    const float* Wl3 = (const float*)d_in[11];
    const float* bl3 = (const float*)d_in[12];
    const void* edge = d_in[13];
    int E = in_sizes[13] / 2;

    float *b1p, *b2p;
    __half *HX, *H1, *H2, *W1H, *W2H, *W3H;
    cudaGetSymbolAddress((void**)&b1p, g_b1p);
    cudaGetSymbolAddress((void**)&b2p, g_b2p);
    cudaGetSymbolAddress((void**)&HX,  g_hx);
    cudaGetSymbolAddress((void**)&H1,  g_h1);
    cudaGetSymbolAddress((void**)&H2,  g_h2);
    cudaGetSymbolAddress((void**)&W1H, g_w1h);
    cudaGetSymbolAddress((void**)&W2H, g_w2h);
    cudaGetSymbolAddress((void**)&W3H, g_w3h);

    const int T = 256;
    int gN = (NN + T - 1) / T;
    int gE = (E + T - 1) / T;

    // setup + unordered-CSR build (R11 structure)
    k_setup<<<(NN * 8 + T - 1) / T, T>>>(x, HX, (const long long*)edge, E);
    k_count<<<gE, T>>>(edge, E);
    k_alloc<<<gN, T>>>();
    k_fill<<<gE, T>>>(edge, E);
    k_padw<<<64, T>>>(W1, W2, W3, b1, b2);

    // ----- Layer 1: agg (64) -> half; wmma 64->112 (+b1,relu), RT=1 (64 rows/blk) -----
    k_aggh<8, 64, false><<<NN * 8 / T, T>>>(HX, H1, nullptr);
    k_gemm_wmma<64, 112, 1, true><<<(NN + 63) / 64, 128>>>(H1, W1H, b1p, H2, NN);

    // ----- Layer 2: wmma 112->64 raw, RT=2 (128 rows/blk); agg (64) +b2,relu -----
    k_gemm_wmma<112, 64, 2, false><<<(NN + 127) / 128, 128>>>(H2, W2H, nullptr, HX, NN);
    k_aggh<8, 64, true><<<NN * 8 / T, T>>>(HX, H1, b2p);

    // ----- Layer 3: wmma 64->32 raw, RT=2; fused agg (32) + MLP epilogue -----
    k_gemm_wmma<64, 32, 2, false><<<(NN + 127) / 128, 128>>>(H1, W3H, nullptr, H2, NN);
    k_agg3_final<<<gN, T>>>(H2, b3, Wl1, bl1, Wl2, bl2, Wl3, bl3, (float*)d_out, NN);
}